// round 1
// baseline (speedup 1.0000x reference)
#include <cuda_runtime.h>

// DAGConstraintLayer: out = tree_min_project(sigmoid(x))
// x: (262144, 127) fp32 row-major. parent(i) = (i-1)/2, complete binary tree depth 7.
//
// Strategy: HBM-bound streaming kernel.
//  - Each block stages 128 rows (128*127 = 16256 floats = 65024 B) into shared
//    memory via fully coalesced float4 copies (4064 float4s, 16B aligned since
//    65024 % 16 == 0).
//  - 128 of the 256 threads then each own one row in smem (row stride 127 words,
//    odd -> bank-conflict-free across the warp) and do the fused pass:
//       r[0] = sigmoid(r[0]); r[i] = min(sigmoid(r[i]), r[(i-1)>>1])  (i ascending)
//    Ascending order == level order since parent index < child index, matching
//    the reference exactly. Dependence chain through smem is only 7 levels deep.
//  - Coalesced float4 store back to global.

#define NUM_NODES 127
#define ROWS_PER_BLOCK 128
#define THREADS 256
#define TILE_FLOATS (ROWS_PER_BLOCK * NUM_NODES)   // 16256
#define TILE_F4 (TILE_FLOATS / 4)                  // 4064
#define TILE_BYTES (TILE_FLOATS * 4)               // 65024

__device__ __forceinline__ float fast_sigmoid(float v) {
    // 1 / (1 + e^-v) : MUFU.EX2 + FMUL + FADD + MUFU.RCP
    return __fdividef(1.0f, 1.0f + __expf(-v));
}

extern __shared__ float tile[];

__global__ void __launch_bounds__(THREADS)
dag_constraint_kernel(const float* __restrict__ x, float* __restrict__ out) {
    const size_t base = (size_t)blockIdx.x * TILE_FLOATS;

    // ---- Phase 1: coalesced gmem -> smem (float4) ----
    const float4* __restrict__ gin = (const float4*)(x + base);
    float4* s4 = (float4*)tile;
    #pragma unroll 4
    for (int i = threadIdx.x; i < TILE_F4; i += THREADS) {
        s4[i] = gin[i];
    }
    __syncthreads();

    // ---- Phase 2: per-row fused sigmoid + tree min-propagation ----
    if (threadIdx.x < ROWS_PER_BLOCK) {
        float* r = tile + threadIdx.x * NUM_NODES;  // odd stride -> conflict-free
        r[0] = fast_sigmoid(r[0]);
        #pragma unroll
        for (int i = 1; i < NUM_NODES; i++) {
            r[i] = fminf(fast_sigmoid(r[i]), r[(i - 1) >> 1]);
        }
    }
    __syncthreads();

    // ---- Phase 3: coalesced smem -> gmem (float4) ----
    float4* __restrict__ gout = (float4*)(out + base);
    #pragma unroll 4
    for (int i = threadIdx.x; i < TILE_F4; i += THREADS) {
        gout[i] = s4[i];
    }
}

extern "C" void kernel_launch(void* const* d_in, const int* in_sizes, int n_in,
                              void* d_out, int out_size) {
    const float* x = (const float*)d_in[0];
    float* out = (float*)d_out;

    const int total = in_sizes[0];                 // 262144 * 127
    const int rows = total / NUM_NODES;            // 262144
    const int grid = rows / ROWS_PER_BLOCK;        // 2048

    // 65 KB dynamic smem needs opt-in (>48 KB). Host-side attribute set; not a
    // stream op, safe during graph capture, deterministic.
    cudaFuncSetAttribute(dag_constraint_kernel,
                         cudaFuncAttributeMaxDynamicSharedMemorySize, TILE_BYTES);

    dag_constraint_kernel<<<grid, THREADS, TILE_BYTES>>>(x, out);
}

// round 2
// speedup vs baseline: 1.0273x; 1.0273x over previous
#include <cuda_runtime.h>

// DAGConstraintLayer: out = tree_min_project(sigmoid(x)) over (262144, 127) fp32.
// parent(i) = (i-1)/2, complete binary tree of depth 7.
//
// Key identity: sigmoid is monotone increasing, so
//    min(sigmoid(a), sigmoid(b)) == sigmoid(min(a, b)).
// => propagate min on RAW x (cheap FMNMX), apply sigmoid once per element in the
//    fully parallel store loop. This matches the reference bit-for-bat in ordering
//    semantics (exact same set of min reductions, then sigmoid).
//
// Structure per CTA (64 rows, 32 KB smem, 256 threads -> 7 CTAs/SM):
//   P1: coalesced float4 gmem->smem (tile base is 16B aligned: 64*127*4 = 32512 = 16*2032)
//   P2: min-propagation. 4 threads per row, one per level-2 subtree (31 nodes each),
//       via fully unrolled register-chain DFS (no LDS-after-STS dependency; the
//       running path-min rides in a register). sub = tid>>6 is warp-uniform -> no
//       divergence. Nodes 1,2 are written redundantly with identical values and
//       read racily — benign because min is idempotent: reading pre- or post-write
//       value yields the same v1.
//   P3: coalesced float4 smem->gmem with sigmoid applied per component (MUFU work
//       spread over all 256 threads, off the critical chain).

#define NUM_NODES 127
#define ROWS_PER_BLOCK 64
#define THREADS 256
#define TILE_FLOATS (ROWS_PER_BLOCK * NUM_NODES)   // 8128
#define TILE_F4 (TILE_FLOATS / 4)                  // 2032
#define TILE_BYTES (TILE_FLOATS * 4)               // 32512

__device__ __forceinline__ float fast_sigmoid(float v) {
    // 1/(1+e^-v): MUFU.EX2 + MUFU.RCP + few FMA
    return __fdividef(1.0f, 1.0f + __expf(-v));
}

// Fully unrolled DFS: node I gets min(r[I], pmin); children inherit the register
// value (no shared-memory round trip on the dependence chain).
template<int I, int REM>
__device__ __forceinline__ void dfs_min(float* __restrict__ r, float pmin) {
    float v = fminf(r[I], pmin);
    r[I] = v;
    if constexpr (REM > 0) {
        dfs_min<2 * I + 1, REM - 1>(r, v);
        dfs_min<2 * I + 2, REM - 1>(r, v);
    }
}

extern __shared__ float tile[];

__global__ void __launch_bounds__(THREADS)
dag_constraint_kernel(const float* __restrict__ x, float* __restrict__ out) {
    const size_t base = (size_t)blockIdx.x * TILE_FLOATS;
    const int tid = threadIdx.x;

    // ---- P1: coalesced load ----
    const float4* __restrict__ gin = (const float4*)(x + base);
    float4* s4 = (float4*)tile;
    #pragma unroll 4
    for (int i = tid; i < TILE_F4; i += THREADS) {
        s4[i] = gin[i];
    }
    __syncthreads();

    // ---- P2: raw min-propagation, 4 subtree-threads per row ----
    {
        const int sub = tid >> 6;     // 0..3, uniform across each warp (no divergence)
        const int row = tid & 63;     // stride-127 rows: conflict-free across a warp
        float* r = tile + row * NUM_NODES;

        const float v0 = r[0];                    // node 0 is never modified
        const int c1 = (sub < 2) ? 1 : 2;         // warp-uniform
        const float v1 = fminf(r[c1], v0);
        if ((sub & 1) == 0) r[c1] = v1;           // single writer; race vs. readers
                                                  // is value-idempotent (see header)
        switch (sub) {                            // warp-uniform switch
            case 0: dfs_min<3, 4>(r, v1); break;  // levels 2..6, 31 nodes
            case 1: dfs_min<4, 4>(r, v1); break;
            case 2: dfs_min<5, 4>(r, v1); break;
            case 3: dfs_min<6, 4>(r, v1); break;
        }
    }
    __syncthreads();

    // ---- P3: sigmoid + coalesced store ----
    float4* __restrict__ gout = (float4*)(out + base);
    #pragma unroll 4
    for (int i = tid; i < TILE_F4; i += THREADS) {
        float4 v = s4[i];
        v.x = fast_sigmoid(v.x);
        v.y = fast_sigmoid(v.y);
        v.z = fast_sigmoid(v.z);
        v.w = fast_sigmoid(v.w);
        gout[i] = v;
    }
}

extern "C" void kernel_launch(void* const* d_in, const int* in_sizes, int n_in,
                              void* d_out, int out_size) {
    const float* x = (const float*)d_in[0];
    float* out = (float*)d_out;

    const int total = in_sizes[0];                 // 262144 * 127
    const int rows = total / NUM_NODES;            // 262144
    const int grid = rows / ROWS_PER_BLOCK;        // 4096

    dag_constraint_kernel<<<grid, THREADS, TILE_BYTES>>>(x, out);
}

// round 3
// speedup vs baseline: 1.2149x; 1.1826x over previous
#include <cuda_runtime.h>

// DAGConstraintLayer: out = tree_min_project(sigmoid(x)) over (262144, 127) fp32.
// parent(i)=(i-1)/2, complete binary tree depth 7.
//
// sigmoid is monotone => min(sig(a),sig(b)) = sig(min(a,b)): propagate min on raw
// x (FMNMX only), apply sigmoid elementwise in the store loop.
//
// R3: persistent CTAs + 2-stage cp.async double-buffered pipeline so DRAM reads
// stream continuously while compute/store phases run (R2 showed bursty loads
// capped DRAM at 58%).
//
// Per tile (32 rows x 127 nodes = 16256 B):
//   load:   cp.async.cg 16B chunks, gmem -> smem (L1 bypass)
//   P2:     8 warps/tile, one per level-3 subtree (15 nodes) per row; lane = row.
//           Top nodes (1,2 and 3..6) handled redundantly with single designated
//           writers; races are value-idempotent under min (readers get the same
//           result from pre- or post-write values).
//   P3:     sigmoid + float4 streaming store.

#define NODES 127
#define ROWS_PER_TILE 32
#define THREADS 256
#define TILE_FLOATS (ROWS_PER_TILE * NODES)   // 4064
#define TILE_F4 (TILE_FLOATS / 4)             // 1016
#define TILE_BYTES (TILE_FLOATS * 4)          // 16256
#define SMEM_BYTES (2 * TILE_BYTES)           // 32512 -> 7 CTAs/SM

__device__ __forceinline__ void cp_async16(void* smem_dst, const void* gmem_src) {
    unsigned s = (unsigned)__cvta_generic_to_shared(smem_dst);
    asm volatile("cp.async.cg.shared.global [%0], [%1], 16;\n" :: "r"(s), "l"(gmem_src));
}
__device__ __forceinline__ void cp_commit() {
    asm volatile("cp.async.commit_group;\n" ::: "memory");
}
template <int N>
__device__ __forceinline__ void cp_wait() {
    asm volatile("cp.async.wait_group %0;\n" :: "n"(N) : "memory");
}

__device__ __forceinline__ float fast_sigmoid(float v) {
    return __fdividef(1.0f, 1.0f + __expf(-v));  // MUFU.EX2 + MUFU.RCP
}

// Fully unrolled register-chain DFS: path-min rides in a register, no
// LDS-after-STS dependence.
template <int I, int REM>
__device__ __forceinline__ void dfs_min(float* __restrict__ r, float pmin) {
    float v = fminf(r[I], pmin);
    r[I] = v;
    if constexpr (REM > 0) {
        dfs_min<2 * I + 1, REM - 1>(r, v);
        dfs_min<2 * I + 2, REM - 1>(r, v);
    }
}

extern __shared__ float smem[];  // 2 tiles

__global__ void __launch_bounds__(THREADS, 7)
dag_constraint_kernel(const float* __restrict__ x, float* __restrict__ out,
                      int ntiles) {
    const int tid = threadIdx.x;
    float* buf0 = smem;
    float* buf1 = smem + TILE_FLOATS;

    const int t0 = blockIdx.x;

    // Prologue: prefetch first tile into buf0.
    if (t0 < ntiles) {
        const float4* __restrict__ src = (const float4*)(x + (size_t)t0 * TILE_FLOATS);
        float4* dst = (float4*)buf0;
        #pragma unroll
        for (int j = tid; j < TILE_F4; j += THREADS) cp_async16(dst + j, src + j);
    }
    cp_commit();

    int stage = 0;
    for (int t = t0; t < ntiles; t += gridDim.x) {
        // Prefetch next tile into the other buffer (its previous contents were
        // fully consumed; end-of-iteration barrier below guarantees it).
        const int nxt = t + gridDim.x;
        float* cur = stage ? buf1 : buf0;
        float* oth = stage ? buf0 : buf1;
        if (nxt < ntiles) {
            const float4* __restrict__ src = (const float4*)(x + (size_t)nxt * TILE_FLOATS);
            float4* dst = (float4*)oth;
            #pragma unroll
            for (int j = tid; j < TILE_F4; j += THREADS) cp_async16(dst + j, src + j);
        }
        cp_commit();
        cp_wait<1>();        // tile t complete (groups retire in order)
        __syncthreads();     // make cp.async data visible across threads

        // ---- P2: raw min-propagation; one warp per level-3 subtree ----
        {
            const int sub = tid >> 5;        // warp id 0..7 (uniform per warp)
            const int lane = tid & 31;       // row within tile
            float* r = cur + lane * NODES;   // odd stride -> bank-conflict-free

            const float v0 = r[0];                   // node 0: read-only
            const int a1 = 1 + (sub >> 2);           // node 1 or 2
            const float v1 = fminf(r[a1], v0);
            if ((sub & 3) == 0) r[a1] = v1;          // subs 0,4 write (idempotent race)
            const int a2 = 3 + (sub >> 1);           // nodes 3..6
            const float v2 = fminf(r[a2], v1);
            if ((sub & 1) == 0) r[a2] = v2;          // subs 0,2,4,6 write
            switch (sub) {                           // warp-uniform
                case 0: dfs_min<7,  3>(r, v2); break;   // 15 nodes each,
                case 1: dfs_min<8,  3>(r, v2); break;   // levels 3..6
                case 2: dfs_min<9,  3>(r, v2); break;
                case 3: dfs_min<10, 3>(r, v2); break;
                case 4: dfs_min<11, 3>(r, v2); break;
                case 5: dfs_min<12, 3>(r, v2); break;
                case 6: dfs_min<13, 3>(r, v2); break;
                case 7: dfs_min<14, 3>(r, v2); break;
            }
        }
        __syncthreads();

        // ---- P3: sigmoid + coalesced streaming store ----
        {
            const float4* s4 = (const float4*)cur;
            float4* __restrict__ gout = (float4*)(out + (size_t)t * TILE_FLOATS);
            #pragma unroll
            for (int j = tid; j < TILE_F4; j += THREADS) {
                float4 v = s4[j];
                v.x = fast_sigmoid(v.x);
                v.y = fast_sigmoid(v.y);
                v.z = fast_sigmoid(v.z);
                v.w = fast_sigmoid(v.w);
                __stcs(gout + j, v);
            }
        }
        __syncthreads();     // all reads of 'cur' done before it's refilled
        stage ^= 1;
    }
}

extern "C" void kernel_launch(void* const* d_in, const int* in_sizes, int n_in,
                              void* d_out, int out_size) {
    const float* x = (const float*)d_in[0];
    float* out = (float*)d_out;

    const int total = in_sizes[0];              // 262144 * 127
    const int rows = total / NODES;             // 262144
    const int ntiles = rows / ROWS_PER_TILE;    // 8192

    int grid = 148 * 7;                         // persistent: 7 CTAs/SM
    if (grid > ntiles) grid = ntiles;

    dag_constraint_kernel<<<grid, THREADS, SMEM_BYTES>>>(x, out, ntiles);
}